// round 8
// baseline (speedup 1.0000x reference)
#include <cuda_runtime.h>
#include <math.h>

// Problem shape (fixed by the reference)
#define NB     16
#define NS     8192
#define NKV    512
#define NE     512
#define NH     8
#define ND     64
#define NCHUNK 8
#define CHUNK  1024
#define TILE   16
#define NTILES (CHUNK/TILE)   // 64
#define TB     512

// Scratch (device globals; allocations forbidden)
__device__ __align__(16) float g_q[NB*NE];
__device__ __align__(16) float g_P[NB*NH*NKV];
__device__ __align__(16) float g_partC[(size_t)NB*NCHUNK*NH*NKV];
__device__ __align__(16) float g_partZ[NB*NCHUNK*NH];
__device__ __align__(16) float g_cbar[NB*NH*NKV];
__device__ __align__(16) float g_ctx[NB*NE];

// ---- packed f32x2 helpers ----
typedef unsigned long long u64;
__device__ __forceinline__ u64 ffma2(u64 a, u64 b, u64 c) {
    u64 d;
    asm("fma.rn.f32x2 %0, %1, %2, %3;" : "=l"(d) : "l"(a), "l"(b), "l"(c));
    return d;
}
__device__ __forceinline__ float lo2(u64 v){ return __uint_as_float((unsigned)v); }
__device__ __forceinline__ float hi2(u64 v){ return __uint_as_float((unsigned)(v>>32)); }
__device__ __forceinline__ u64 dup2(float v){
    u64 r; asm("mov.b64 %0, {%1, %1};" : "=l"(r) : "f"(v)); return r;
}
__device__ __forceinline__ void cpa16(unsigned dst, const void* src){
    asm volatile("cp.async.cg.shared.global [%0], [%1], 16;" :: "r"(dst), "l"(src));
}

// ---------------------------------------------------------------------------
// A1: q[b,e] = query[b,:] @ Wq[:,e] + bq[e].
// grid (16 b, 8 eblocks of 64) x 256 = 64 cols x 4-way split-K, MLP8.
// ---------------------------------------------------------------------------
__global__ void __launch_bounds__(256) kernA1(
    const float* __restrict__ query, const float* __restrict__ Wq,
    const float* __restrict__ bq)
{
    __shared__ float qs[NKV];
    __shared__ float red[256];
    const int b = blockIdx.x, eb = blockIdx.y, t = threadIdx.x;
    for (int i = t; i < NKV; i += 256) qs[i] = query[b*NKV + i];
    __syncthreads();
    const int e = eb*64 + (t & 63), kp = t >> 6;
    const float* q  = qs + kp*128;
    const float* wq = Wq + (size_t)(kp*128)*NE + e;
    float s0=0,s1=0,s2=0,s3=0,s4=0,s5=0,s6=0,s7=0;
    #pragma unroll 4
    for (int j = 0; j < 128; j += 8) {
        s0 = fmaf(q[j+0], wq[(size_t)(j+0)*NE], s0);
        s1 = fmaf(q[j+1], wq[(size_t)(j+1)*NE], s1);
        s2 = fmaf(q[j+2], wq[(size_t)(j+2)*NE], s2);
        s3 = fmaf(q[j+3], wq[(size_t)(j+3)*NE], s3);
        s4 = fmaf(q[j+4], wq[(size_t)(j+4)*NE], s4);
        s5 = fmaf(q[j+5], wq[(size_t)(j+5)*NE], s5);
        s6 = fmaf(q[j+6], wq[(size_t)(j+6)*NE], s6);
        s7 = fmaf(q[j+7], wq[(size_t)(j+7)*NE], s7);
    }
    red[t] = ((s0+s1)+(s2+s3))+((s4+s5)+(s6+s7));
    __syncthreads();
    if (t < 64)
        g_q[b*NE + e] = ((red[t]+red[t+64])+(red[t+128]+red[t+192])) + bq[e];
}

// ---------------------------------------------------------------------------
// A2: P[b,h,j] = 0.125 * sum_d g_q[b,h*64+d] * Wk[j,h*64+d]
// ---------------------------------------------------------------------------
__global__ void __launch_bounds__(256) kernA2(const float* __restrict__ Wk)
{
    __shared__ float wks[64*65];
    __shared__ float qhs[16*64];
    const int jb = blockIdx.x, h = blockIdx.y, t = threadIdx.x;

    for (int i = t; i < 64*16; i += 256) {
        int j = i >> 4, d4 = i & 15;
        float4 v = *(const float4*)(Wk + (size_t)(jb*64 + j)*NE + h*ND + d4*4);
        wks[j*65 + d4*4+0] = v.x; wks[j*65 + d4*4+1] = v.y;
        wks[j*65 + d4*4+2] = v.z; wks[j*65 + d4*4+3] = v.w;
    }
    for (int i = t; i < 16*64; i += 256) {
        int bb = i >> 6, d = i & 63;
        qhs[bb*64 + d] = g_q[bb*NE + h*ND + d];
    }
    __syncthreads();

    const int j = t & 63, bg = t >> 6;
    float acc[4] = {0.f,0.f,0.f,0.f};
    const float* wr = wks + j*65;
    #pragma unroll
    for (int d = 0; d < 64; ++d) {
        float wv = wr[d];
        #pragma unroll
        for (int bb = 0; bb < 4; ++bb)
            acc[bb] = fmaf(wv, qhs[(bg*4 + bb)*64 + d], acc[bb]);
    }
    #pragma unroll
    for (int bb = 0; bb < 4; ++bb)
        g_P[((size_t)(bg*4 + bb)*NH + h)*NKV + jb*64 + j] = acc[bb]*0.125f;
}

// ---------------------------------------------------------------------------
// B: fused single-phase pass over kv. 512 threads / 16 warps (4 per SMSP).
// warp w: rows rb*4..+3 (rb=w>>2), heads hg*2..+1 (hg=w&3).
// Per 2-row subgroup: kv row chunks live in registers, used for BOTH the
// logit dot (fold 16/8/4 + 2-stage reduce-scatter + exp + shuffle broadcast)
// and the weighted accumulation into a 2-head x 16-col register tile.
// No-max softmax (|logit| < ~3). Triple-buffered cp.async ring.
// ---------------------------------------------------------------------------
__global__ void __launch_bounds__(TB, 1) kernB(const float* __restrict__ kv)
{
    extern __shared__ float sh[];
    float* kvs = sh;                 // [3][TILE][NKV] (reused as reduce buffer)
    float* zs  = sh + 3*TILE*NKV;    // [64]

    const int tid  = threadIdx.x;
    const int wid  = tid >> 5, lane = tid & 31;
    const int rb = wid >> 2, hg = wid & 3;
    const int chunk = blockIdx.x, b = blockIdx.y;

    // P slice in registers: 2 heads x 4 chunks x 4 floats (per lane)
    u64 Pr[2][4][2];
    #pragma unroll
    for (int h = 0; h < 2; ++h)
        #pragma unroll
        for (int c = 0; c < 4; ++c) {
            const float* p = g_P + ((size_t)b*NH + hg*2 + h)*NKV + c*128 + lane*4;
            ulonglong2 v = *(const ulonglong2*)p;
            Pr[h][c][0] = v.x; Pr[h][c][1] = v.y;
        }

    u64 acc[2][4][2];
    #pragma unroll
    for (int h = 0; h < 2; ++h)
        #pragma unroll
        for (int c = 0; c < 4; ++c) { acc[h][c][0] = 0ull; acc[h][c][1] = 0ull; }
    float zacc = 0.f;

    const unsigned kvs_u = (unsigned)__cvta_generic_to_shared(kvs);
    const float4* src_base = (const float4*)kv
        + ((size_t)b*NS + (size_t)chunk*CHUNK)*(NKV/4);

    // prologue: stage tiles 0 and 1
    #pragma unroll
    for (int pt = 0; pt < 2; ++pt) {
        const float4* s = src_base + (size_t)pt*TILE*(NKV/4);
        unsigned dst = kvs_u + (unsigned)(pt*TILE*NKV*4);
        #pragma unroll
        for (int k = 0; k < (TILE*NKV/4)/TB; ++k) {
            int i = tid + k*TB;
            cpa16(dst + (unsigned)i*16u, s + i);
        }
        asm volatile("cp.async.commit_group;");
    }

    for (int t = 0; t < NTILES; ++t) {
        if (t < NTILES-1) asm volatile("cp.async.wait_group 1;");
        else              asm volatile("cp.async.wait_group 0;");
        __syncthreads();

        if (t + 2 < NTILES) {   // stage t+2 into buffer (t+2)%3
            const float4* s = src_base + (size_t)(t+2)*TILE*(NKV/4);
            unsigned dst = kvs_u + (unsigned)(((t+2)%3)*TILE*NKV*4);
            #pragma unroll
            for (int k = 0; k < (TILE*NKV/4)/TB; ++k) {
                int i = tid + k*TB;
                cpa16(dst + (unsigned)i*16u, s + i);
            }
            asm volatile("cp.async.commit_group;");
        }

        const float* kbw = kvs + (t%3)*TILE*NKV + rb*4*NKV;
        #pragma unroll
        for (int sub = 0; sub < 2; ++sub) {
            // load 2 rows into registers (reused by both stages)
            ulonglong2 x[2][4];
            #pragma unroll
            for (int r = 0; r < 2; ++r)
                #pragma unroll
                for (int c = 0; c < 4; ++c)
                    x[r][c] = *(const ulonglong2*)(kbw + (sub*2+r)*NKV + c*128 + lane*4);

            // logits: 2 rows x 2 heads
            u64 la[2][2];
            #pragma unroll
            for (int r = 0; r < 2; ++r)
                #pragma unroll
                for (int h = 0; h < 2; ++h) la[r][h] = 0ull;
            #pragma unroll
            for (int c = 0; c < 4; ++c)
                #pragma unroll
                for (int r = 0; r < 2; ++r)
                    #pragma unroll
                    for (int h = 0; h < 2; ++h) {
                        la[r][h] = ffma2(x[r][c].x, Pr[h][c][0], la[r][h]);
                        la[r][h] = ffma2(x[r][c].y, Pr[h][c][1], la[r][h]);
                    }
            float v[4];
            #pragma unroll
            for (int r = 0; r < 2; ++r)
                #pragma unroll
                for (int h = 0; h < 2; ++h)
                    v[r*2+h] = lo2(la[r][h]) + hi2(la[r][h]);
            // fold lane bits 4,3,2 into bits 1..0 groups
            #pragma unroll
            for (int j = 0; j < 4; ++j) v[j] += __shfl_xor_sync(0xffffffffu, v[j], 16);
            #pragma unroll
            for (int j = 0; j < 4; ++j) v[j] += __shfl_xor_sync(0xffffffffu, v[j], 8);
            #pragma unroll
            for (int j = 0; j < 4; ++j) v[j] += __shfl_xor_sync(0xffffffffu, v[j], 4);
            // reduce-scatter over 4: lane l ends with idx (l&3) = r*2+h
            #pragma unroll
            for (int half = 2; half >= 1; half >>= 1) {
                const bool up = (lane & half) != 0;
                #pragma unroll
                for (int j = 0; j < half; ++j) {
                    float mine   = up ? v[j+half] : v[j];
                    float theirs = up ? v[j]      : v[j+half];
                    v[j] = mine + __shfl_xor_sync(0xffffffffu, theirs, half);
                }
            }
            float w = __expf(v[0]);        // idx = lane&3: r=(idx>>1), h=idx&1
            if (lane < 4) zacc += w;
            // broadcast the 4 weights, duplicate for f32x2
            u64 wd[2][2];
            #pragma unroll
            for (int i = 0; i < 4; ++i) {
                float wi = __shfl_sync(0xffffffffu, w, i);
                wd[i>>1][i&1] = dup2(wi);
            }
            // weighted accumulation (reuses x registers)
            #pragma unroll
            for (int c = 0; c < 4; ++c)
                #pragma unroll
                for (int r = 0; r < 2; ++r)
                    #pragma unroll
                    for (int h = 0; h < 2; ++h) {
                        acc[h][c][0] = ffma2(wd[r][h], x[r][c].x, acc[h][c][0]);
                        acc[h][c][1] = ffma2(wd[r][h], x[r][c].y, acc[h][c][1]);
                    }
        }
    }

    // ---- epilogue: cross-warp reduce via smem (kvs is free now) ----
    // Each warp owns a 1024-float region: [2 heads][512 cols]. Total 16
    // warps x 1024 = 16384 floats < 24576-float kv ring: in-bounds.
    __syncthreads();
    {
        float* red = kvs + wid*1024;
        #pragma unroll
        for (int h = 0; h < 2; ++h)
            #pragma unroll
            for (int c = 0; c < 4; ++c)
                *(ulonglong2*)(red + h*NKV + c*128 + lane*4)
                    = make_ulonglong2(acc[h][c][0], acc[h][c][1]);
        if (lane < 4) zs[wid*4 + lane] = zacc;
    }
    __syncthreads();

    const int part = b*NCHUNK + chunk;
    {
        float4* pc = (float4*)(g_partC + (size_t)part*NH*NKV);
        const float4* redv = (const float4*)kvs;   // warp stride 256 float4
        for (int s = tid; s < NH*NKV/4; s += TB) {
            const int h = s >> 7, col4 = s & 127;
            const int hg2 = h >> 1, hl = h & 1;    // warp = rb*4 + hg2
            float4 a0 = redv[(0*4+hg2)*256 + hl*128 + col4];
            float4 a1 = redv[(1*4+hg2)*256 + hl*128 + col4];
            float4 a2 = redv[(2*4+hg2)*256 + hl*128 + col4];
            float4 a3 = redv[(3*4+hg2)*256 + hl*128 + col4];
            a0.x += a1.x + a2.x + a3.x;
            a0.y += a1.y + a2.y + a3.y;
            a0.z += a1.z + a2.z + a3.z;
            a0.w += a1.w + a2.w + a3.w;
            pc[s] = a0;
        }
    }
    if (tid < NH) {
        const int hg2 = tid >> 1, hl = tid & 1;
        float Z = 0.f;
        #pragma unroll
        for (int rbi = 0; rbi < 4; ++rbi) {
            const int wi = rbi*4 + hg2;
            Z += zs[wi*4 + 0*2 + hl] + zs[wi*4 + 1*2 + hl];
        }
        g_partZ[part*NH + tid] = Z;
    }
}

// ---------------------------------------------------------------------------
// C1: cbar[b,h,j] = (sum_i partC[b,i,h,j]) / Z[b,h].  grid 64 x 256
// ---------------------------------------------------------------------------
__global__ void __launch_bounds__(256) kernC1()
{
    const int idx = blockIdx.x*256 + threadIdx.x;      // 16384 float4 slots
    const int b = idx >> 10, rem = idx & 1023, h = rem >> 7, j4 = rem & 127;
    float Z = 0.f;
    #pragma unroll
    for (int i = 0; i < NCHUNK; ++i) Z += g_partZ[(b*NCHUNK + i)*NH + h];
    const float invZ = 1.0f / Z;
    float4 s = make_float4(0.f,0.f,0.f,0.f);
    #pragma unroll
    for (int i = 0; i < NCHUNK; ++i) {
        const float4* p = (const float4*)(g_partC + (((size_t)(b*NCHUNK + i)*NH + h) << 9));
        float4 v = p[j4];
        s.x += v.x; s.y += v.y; s.z += v.z; s.w += v.w;
    }
    s.x *= invZ; s.y *= invZ; s.z *= invZ; s.w *= invZ;
    ((float4*)g_cbar)[((size_t)(b*NH + h) << 7) + j4] = s;
}

// ---------------------------------------------------------------------------
// C2: ctx[b, h*64+col] = cbar[b,h,:] @ Wv[:, h*64+col] + bv.
// grid (16 b, 8 h) x 256 = 64 cols x 4-way split-K, MLP8.
// ---------------------------------------------------------------------------
__global__ void __launch_bounds__(256) kernC2(
    const float* __restrict__ Wv, const float* __restrict__ bv)
{
    __shared__ float cb_s[NKV];
    __shared__ float red[256];
    const int b = blockIdx.x, h = blockIdx.y, t = threadIdx.x;
    for (int i = t; i < NKV; i += 256) cb_s[i] = g_cbar[(size_t)(b*NH + h)*NKV + i];
    __syncthreads();
    const int col = h*64 + (t & 63), kp = t >> 6;
    const float* c  = cb_s + kp*128;
    const float* wv = Wv + (size_t)(kp*128)*NE + col;
    float s0=0,s1=0,s2=0,s3=0,s4=0,s5=0,s6=0,s7=0;
    #pragma unroll 4
    for (int j = 0; j < 128; j += 8) {
        s0 = fmaf(c[j+0], wv[(size_t)(j+0)*NE], s0);
        s1 = fmaf(c[j+1], wv[(size_t)(j+1)*NE], s1);
        s2 = fmaf(c[j+2], wv[(size_t)(j+2)*NE], s2);
        s3 = fmaf(c[j+3], wv[(size_t)(j+3)*NE], s3);
        s4 = fmaf(c[j+4], wv[(size_t)(j+4)*NE], s4);
        s5 = fmaf(c[j+5], wv[(size_t)(j+5)*NE], s5);
        s6 = fmaf(c[j+6], wv[(size_t)(j+6)*NE], s6);
        s7 = fmaf(c[j+7], wv[(size_t)(j+7)*NE], s7);
    }
    red[t] = ((s0+s1)+(s2+s3))+((s4+s5)+(s6+s7));
    __syncthreads();
    if (t < 64)
        g_ctx[b*NE + col] = ((red[t]+red[t+64])+(red[t+128]+red[t+192])) + bv[col];
}

// ---------------------------------------------------------------------------
// D: out[b] = ctx[b] @ Wo + bo.  grid (16 b, 8 colblocks) x 256, MLP8.
// ---------------------------------------------------------------------------
__global__ void __launch_bounds__(256) kernD(
    const float* __restrict__ Wo, const float* __restrict__ bo,
    float* __restrict__ out)
{
    __shared__ float cs[NE];
    __shared__ float red[256];
    const int b = blockIdx.x, cb = blockIdx.y, t = threadIdx.x;
    for (int i = t; i < NE; i += 256) cs[i] = g_ctx[b*NE + i];
    __syncthreads();
    const int col = cb*64 + (t & 63), kp = t >> 6;
    const float* c  = cs + kp*128;
    const float* wo = Wo + (size_t)(kp*128)*NE + col;
    float s0=0,s1=0,s2=0,s3=0,s4=0,s5=0,s6=0,s7=0;
    #pragma unroll 4
    for (int j = 0; j < 128; j += 8) {
        s0 = fmaf(c[j+0], wo[(size_t)(j+0)*NE], s0);
        s1 = fmaf(c[j+1], wo[(size_t)(j+1)*NE], s1);
        s2 = fmaf(c[j+2], wo[(size_t)(j+2)*NE], s2);
        s3 = fmaf(c[j+3], wo[(size_t)(j+3)*NE], s3);
        s4 = fmaf(c[j+4], wo[(size_t)(j+4)*NE], s4);
        s5 = fmaf(c[j+5], wo[(size_t)(j+5)*NE], s5);
        s6 = fmaf(c[j+6], wo[(size_t)(j+6)*NE], s6);
        s7 = fmaf(c[j+7], wo[(size_t)(j+7)*NE], s7);
    }
    red[t] = ((s0+s1)+(s2+s3))+((s4+s5)+(s6+s7));
    __syncthreads();
    if (t < 64)
        out[b*NE + col] = ((red[t]+red[t+64])+(red[t+128]+red[t+192])) + bo[col];
}

// ---------------------------------------------------------------------------
extern "C" void kernel_launch(void* const* d_in, const int* in_sizes, int n_in,
                              void* d_out, int out_size)
{
    (void)in_sizes; (void)n_in; (void)out_size;
    const float* query = (const float*)d_in[0];
    const float* kv    = (const float*)d_in[1];
    const float* Wq    = (const float*)d_in[2];
    const float* bq    = (const float*)d_in[3];
    const float* Wk    = (const float*)d_in[4];
    // d_in[5] = bk: softmax-invariant, unused
    const float* Wv    = (const float*)d_in[6];
    const float* bv    = (const float*)d_in[7];
    const float* Wo    = (const float*)d_in[8];
    const float* bo    = (const float*)d_in[9];
    float* out = (float*)d_out;

    const size_t shmB = (size_t)(3*TILE*NKV + 64) * sizeof(float);
    cudaFuncSetAttribute(kernB, cudaFuncAttributeMaxDynamicSharedMemorySize, (int)shmB);

    kernA1<<<dim3(NB, 8), 256>>>(query, Wq, bq);
    kernA2<<<dim3(8, NH), 256>>>(Wk);
    kernB <<<dim3(NCHUNK, NB), TB, shmB>>>(kv);
    kernC1<<<64, 256>>>();
    kernC2<<<dim3(NB, NH), 256>>>(Wv, bv);
    kernD <<<dim3(NB, 8), 256>>>(Wo, bo, out);
}

// round 9
// speedup vs baseline: 1.1196x; 1.1196x over previous
#include <cuda_runtime.h>
#include <math.h>

// Problem shape (fixed by the reference)
#define NB     16
#define NS     8192
#define NKV    512
#define NE     512
#define NH     8
#define ND     64
#define NCHUNK 8
#define CHUNK  1024
#define TILE   32
#define NTILES (CHUNK/TILE)   // 32
#define TB     256

// Scratch (device globals; allocations forbidden)
__device__ __align__(16) float g_q[NB*NE];
__device__ __align__(16) float g_P[NB*NH*NKV];
__device__ __align__(16) float g_partC[(size_t)NB*NCHUNK*NH*NKV];
__device__ __align__(16) float g_partZ[NB*NCHUNK*NH];
__device__ __align__(16) float g_cbar[NB*NH*NKV];
__device__ __align__(16) float g_ctx[NB*NE];

// ---- packed f32x2 helpers ----
typedef unsigned long long u64;
__device__ __forceinline__ u64 ffma2(u64 a, u64 b, u64 c) {
    u64 d;
    asm("fma.rn.f32x2 %0, %1, %2, %3;" : "=l"(d) : "l"(a), "l"(b), "l"(c));
    return d;
}
__device__ __forceinline__ float lo2(u64 v){ return __uint_as_float((unsigned)v); }
__device__ __forceinline__ float hi2(u64 v){ return __uint_as_float((unsigned)(v>>32)); }
__device__ __forceinline__ u64 dup2(float v){
    u64 r; asm("mov.b64 %0, {%1, %1};" : "=l"(r) : "f"(v)); return r;
}
__device__ __forceinline__ void cpa16(unsigned dst, const void* src){
    asm volatile("cp.async.cg.shared.global [%0], [%1], 16;" :: "r"(dst), "l"(src));
}

// ---------------------------------------------------------------------------
// A1: q[b,e] = query[b,:] @ Wq[:,e] + bq[e].
// grid (16 b, 8 eblocks of 64) x 256 = 64 cols x 4-way split-K, MLP8.
// ---------------------------------------------------------------------------
__global__ void __launch_bounds__(256) kernA1(
    const float* __restrict__ query, const float* __restrict__ Wq,
    const float* __restrict__ bq)
{
    __shared__ float qs[NKV];
    __shared__ float red[256];
    const int b = blockIdx.x, eb = blockIdx.y, t = threadIdx.x;
    for (int i = t; i < NKV; i += 256) qs[i] = query[b*NKV + i];
    __syncthreads();
    const int e = eb*64 + (t & 63), kp = t >> 6;
    const float* q  = qs + kp*128;
    const float* wq = Wq + (size_t)(kp*128)*NE + e;
    float s0=0,s1=0,s2=0,s3=0,s4=0,s5=0,s6=0,s7=0;
    #pragma unroll 4
    for (int j = 0; j < 128; j += 8) {
        s0 = fmaf(q[j+0], wq[(size_t)(j+0)*NE], s0);
        s1 = fmaf(q[j+1], wq[(size_t)(j+1)*NE], s1);
        s2 = fmaf(q[j+2], wq[(size_t)(j+2)*NE], s2);
        s3 = fmaf(q[j+3], wq[(size_t)(j+3)*NE], s3);
        s4 = fmaf(q[j+4], wq[(size_t)(j+4)*NE], s4);
        s5 = fmaf(q[j+5], wq[(size_t)(j+5)*NE], s5);
        s6 = fmaf(q[j+6], wq[(size_t)(j+6)*NE], s6);
        s7 = fmaf(q[j+7], wq[(size_t)(j+7)*NE], s7);
    }
    red[t] = ((s0+s1)+(s2+s3))+((s4+s5)+(s6+s7));
    __syncthreads();
    if (t < 64)
        g_q[b*NE + e] = ((red[t]+red[t+64])+(red[t+128]+red[t+192])) + bq[e];
}

// ---------------------------------------------------------------------------
// A2: P[b,h,j] = 0.125 * sum_d g_q[b,h*64+d] * Wk[j,h*64+d]
// ---------------------------------------------------------------------------
__global__ void __launch_bounds__(256) kernA2(const float* __restrict__ Wk)
{
    __shared__ float wks[64*65];
    __shared__ float qhs[16*64];
    const int jb = blockIdx.x, h = blockIdx.y, t = threadIdx.x;

    for (int i = t; i < 64*16; i += 256) {
        int j = i >> 4, d4 = i & 15;
        float4 v = *(const float4*)(Wk + (size_t)(jb*64 + j)*NE + h*ND + d4*4);
        wks[j*65 + d4*4+0] = v.x; wks[j*65 + d4*4+1] = v.y;
        wks[j*65 + d4*4+2] = v.z; wks[j*65 + d4*4+3] = v.w;
    }
    for (int i = t; i < 16*64; i += 256) {
        int bb = i >> 6, d = i & 63;
        qhs[bb*64 + d] = g_q[bb*NE + h*ND + d];
    }
    __syncthreads();

    const int j = t & 63, bg = t >> 6;
    float acc[4] = {0.f,0.f,0.f,0.f};
    const float* wr = wks + j*65;
    #pragma unroll
    for (int d = 0; d < 64; ++d) {
        float wv = wr[d];
        #pragma unroll
        for (int bb = 0; bb < 4; ++bb)
            acc[bb] = fmaf(wv, qhs[(bg*4 + bb)*64 + d], acc[bb]);
    }
    #pragma unroll
    for (int bb = 0; bb < 4; ++bb)
        g_P[((size_t)(bg*4 + bb)*NH + h)*NKV + jb*64 + j] = acc[bb]*0.125f;
}

// ---------------------------------------------------------------------------
// B: fused single-phase pass over kv. 256 threads / 8 warps (2 per SMSP),
// 256 regs/thread budget. warp w: rows rb*8..+7 (rb=w>>1), heads hg*4..+3
// (hg=w&1). Tile = 32 rows; each warp processes its 8 rows as two merged
// 4-row groups: one 16-value butterfly (fold16 + scatter 8/4/2/1) produces
// all 16 logits, one exp per lane, w broadcast fused into the accumulation.
// kv rows live in registers and feed BOTH the logit dot and the weighted
// accumulation. No-max softmax (|logit| < ~3). Triple-buffered cp.async.
// ---------------------------------------------------------------------------
__global__ void __launch_bounds__(TB, 1) kernB(const float* __restrict__ kv)
{
    extern __shared__ float sh[];
    float* kvs = sh;                 // [3][TILE][NKV] (reused as reduce buffer)
    float* zs  = sh + 3*TILE*NKV;    // [128]

    const int tid  = threadIdx.x;
    const int wid  = tid >> 5, lane = tid & 31;
    const int rb = wid >> 1, hg = wid & 1;
    const int chunk = blockIdx.x, b = blockIdx.y;

    // P slice in registers: 4 heads x 4 chunks x 4 floats (per lane)
    u64 Pr[4][4][2];
    #pragma unroll
    for (int h = 0; h < 4; ++h)
        #pragma unroll
        for (int c = 0; c < 4; ++c) {
            const float* p = g_P + ((size_t)b*NH + hg*4 + h)*NKV + c*128 + lane*4;
            ulonglong2 v = *(const ulonglong2*)p;
            Pr[h][c][0] = v.x; Pr[h][c][1] = v.y;
        }

    u64 acc[4][4][2];
    #pragma unroll
    for (int h = 0; h < 4; ++h)
        #pragma unroll
        for (int c = 0; c < 4; ++c) { acc[h][c][0] = 0ull; acc[h][c][1] = 0ull; }
    float zacc = 0.f;

    const unsigned kvs_u = (unsigned)__cvta_generic_to_shared(kvs);
    const float4* src_base = (const float4*)kv
        + ((size_t)b*NS + (size_t)chunk*CHUNK)*(NKV/4);

    // prologue: stage tiles 0 and 1
    #pragma unroll
    for (int pt = 0; pt < 2; ++pt) {
        const float4* s = src_base + (size_t)pt*TILE*(NKV/4);
        unsigned dst = kvs_u + (unsigned)(pt*TILE*NKV*4);
        #pragma unroll
        for (int k = 0; k < (TILE*NKV/4)/TB; ++k) {
            int i = tid + k*TB;
            cpa16(dst + (unsigned)i*16u, s + i);
        }
        asm volatile("cp.async.commit_group;");
    }

    for (int t = 0; t < NTILES; ++t) {
        if (t < NTILES-1) asm volatile("cp.async.wait_group 1;");
        else              asm volatile("cp.async.wait_group 0;");
        __syncthreads();

        if (t + 2 < NTILES) {   // stage t+2 into buffer (t+2)%3
            const float4* s = src_base + (size_t)(t+2)*TILE*(NKV/4);
            unsigned dst = kvs_u + (unsigned)(((t+2)%3)*TILE*NKV*4);
            #pragma unroll
            for (int k = 0; k < (TILE*NKV/4)/TB; ++k) {
                int i = tid + k*TB;
                cpa16(dst + (unsigned)i*16u, s + i);
            }
            asm volatile("cp.async.commit_group;");
        }

        const float* kbw = kvs + (t%3)*TILE*NKV + rb*8*NKV;
        #pragma unroll
        for (int g = 0; g < 2; ++g) {
            // load 4 rows into registers (reused by both stages)
            ulonglong2 x[4][4];
            #pragma unroll
            for (int r = 0; r < 4; ++r)
                #pragma unroll
                for (int c = 0; c < 4; ++c)
                    x[r][c] = *(const ulonglong2*)(kbw + (g*4+r)*NKV + c*128 + lane*4);

            // logits: 4 rows x 4 heads
            u64 la[4][4];
            #pragma unroll
            for (int r = 0; r < 4; ++r)
                #pragma unroll
                for (int h = 0; h < 4; ++h) la[r][h] = 0ull;
            #pragma unroll
            for (int c = 0; c < 4; ++c)
                #pragma unroll
                for (int r = 0; r < 4; ++r)
                    #pragma unroll
                    for (int h = 0; h < 4; ++h) {
                        la[r][h] = ffma2(x[r][c].x, Pr[h][c][0], la[r][h]);
                        la[r][h] = ffma2(x[r][c].y, Pr[h][c][1], la[r][h]);
                    }
            float v[16];
            #pragma unroll
            for (int r = 0; r < 4; ++r)
                #pragma unroll
                for (int h = 0; h < 4; ++h)
                    v[r*4+h] = lo2(la[r][h]) + hi2(la[r][h]);
            // fold upper half-warp, then reduce-scatter over 16 lanes:
            // lane l (l<16) ends with full logit of index l = r*4+h
            #pragma unroll
            for (int j = 0; j < 16; ++j) v[j] += __shfl_xor_sync(0xffffffffu, v[j], 16);
            #pragma unroll
            for (int half = 8; half >= 1; half >>= 1) {
                const bool up = (lane & half) != 0;
                #pragma unroll
                for (int j = 0; j < half; ++j) {
                    float mine   = up ? v[j+half] : v[j];
                    float theirs = up ? v[j]      : v[j+half];
                    v[j] = mine + __shfl_xor_sync(0xffffffffu, theirs, half);
                }
            }
            float w = __expf(v[0]);        // idx = lane&15: r=(idx>>2), h=idx&3
            if (lane < 16) zacc += w;
            // weighted accumulation; w broadcast fused per (r,h)
            #pragma unroll
            for (int r = 0; r < 4; ++r)
                #pragma unroll
                for (int h = 0; h < 4; ++h) {
                    u64 wd = dup2(__shfl_sync(0xffffffffu, w, r*4 + h));
                    #pragma unroll
                    for (int c = 0; c < 4; ++c) {
                        acc[h][c][0] = ffma2(wd, x[r][c].x, acc[h][c][0]);
                        acc[h][c][1] = ffma2(wd, x[r][c].y, acc[h][c][1]);
                    }
                }
        }
    }

    // ---- epilogue: cross-warp reduce via smem (kvs is free now) ----
    // Each warp owns 2048 floats: [4 heads][512 cols]; 8 warps = 16384
    // floats < 49152-float kv ring: in-bounds.
    __syncthreads();
    {
        float* red = kvs + wid*2048;
        #pragma unroll
        for (int h = 0; h < 4; ++h)
            #pragma unroll
            for (int c = 0; c < 4; ++c)
                *(ulonglong2*)(red + h*NKV + c*128 + lane*4)
                    = make_ulonglong2(acc[h][c][0], acc[h][c][1]);
        if (lane < 16) zs[wid*16 + lane] = zacc;
    }
    __syncthreads();

    const int part = b*NCHUNK + chunk;
    {
        float4* pc = (float4*)(g_partC + (size_t)part*NH*NKV);
        const float4* redv = (const float4*)kvs;   // warp stride 512 float4
        for (int s = tid; s < NH*NKV/4; s += TB) {
            const int h = s >> 7, col4 = s & 127;
            const int hg2 = h >> 2, hl = h & 3;    // warp = rbi*2 + hg2
            float4 a0 = redv[(0*2+hg2)*512 + hl*128 + col4];
            float4 a1 = redv[(1*2+hg2)*512 + hl*128 + col4];
            float4 a2 = redv[(2*2+hg2)*512 + hl*128 + col4];
            float4 a3 = redv[(3*2+hg2)*512 + hl*128 + col4];
            a0.x += a1.x + a2.x + a3.x;
            a0.y += a1.y + a2.y + a3.y;
            a0.z += a1.z + a2.z + a3.z;
            a0.w += a1.w + a2.w + a3.w;
            pc[s] = a0;
        }
    }
    if (tid < NH) {
        const int hg2 = tid >> 2, hl = tid & 3;
        float Z = 0.f;
        #pragma unroll
        for (int rbi = 0; rbi < 4; ++rbi) {
            const int wi = rbi*2 + hg2;
            Z += (zs[wi*16 + hl] + zs[wi*16 + 4 + hl])
               + (zs[wi*16 + 8 + hl] + zs[wi*16 + 12 + hl]);
        }
        g_partZ[part*NH + tid] = Z;
    }
}

// ---------------------------------------------------------------------------
// C1: cbar[b,h,j] = (sum_i partC[b,i,h,j]) / Z[b,h].  grid 64 x 256
// ---------------------------------------------------------------------------
__global__ void __launch_bounds__(256) kernC1()
{
    const int idx = blockIdx.x*256 + threadIdx.x;      // 16384 float4 slots
    const int b = idx >> 10, rem = idx & 1023, h = rem >> 7, j4 = rem & 127;
    float Z = 0.f;
    #pragma unroll
    for (int i = 0; i < NCHUNK; ++i) Z += g_partZ[(b*NCHUNK + i)*NH + h];
    const float invZ = 1.0f / Z;
    float4 s = make_float4(0.f,0.f,0.f,0.f);
    #pragma unroll
    for (int i = 0; i < NCHUNK; ++i) {
        const float4* p = (const float4*)(g_partC + (((size_t)(b*NCHUNK + i)*NH + h) << 9));
        float4 v = p[j4];
        s.x += v.x; s.y += v.y; s.z += v.z; s.w += v.w;
    }
    s.x *= invZ; s.y *= invZ; s.z *= invZ; s.w *= invZ;
    ((float4*)g_cbar)[((size_t)(b*NH + h) << 7) + j4] = s;
}

// ---------------------------------------------------------------------------
// C2: ctx[b, h*64+col] = cbar[b,h,:] @ Wv[:, h*64+col] + bv.
// grid (16 b, 8 h) x 256 = 64 cols x 4-way split-K, MLP8.
// ---------------------------------------------------------------------------
__global__ void __launch_bounds__(256) kernC2(
    const float* __restrict__ Wv, const float* __restrict__ bv)
{
    __shared__ float cb_s[NKV];
    __shared__ float red[256];
    const int b = blockIdx.x, h = blockIdx.y, t = threadIdx.x;
    for (int i = t; i < NKV; i += 256) cb_s[i] = g_cbar[(size_t)(b*NH + h)*NKV + i];
    __syncthreads();
    const int col = h*64 + (t & 63), kp = t >> 6;
    const float* c  = cb_s + kp*128;
    const float* wv = Wv + (size_t)(kp*128)*NE + col;
    float s0=0,s1=0,s2=0,s3=0,s4=0,s5=0,s6=0,s7=0;
    #pragma unroll 4
    for (int j = 0; j < 128; j += 8) {
        s0 = fmaf(c[j+0], wv[(size_t)(j+0)*NE], s0);
        s1 = fmaf(c[j+1], wv[(size_t)(j+1)*NE], s1);
        s2 = fmaf(c[j+2], wv[(size_t)(j+2)*NE], s2);
        s3 = fmaf(c[j+3], wv[(size_t)(j+3)*NE], s3);
        s4 = fmaf(c[j+4], wv[(size_t)(j+4)*NE], s4);
        s5 = fmaf(c[j+5], wv[(size_t)(j+5)*NE], s5);
        s6 = fmaf(c[j+6], wv[(size_t)(j+6)*NE], s6);
        s7 = fmaf(c[j+7], wv[(size_t)(j+7)*NE], s7);
    }
    red[t] = ((s0+s1)+(s2+s3))+((s4+s5)+(s6+s7));
    __syncthreads();
    if (t < 64)
        g_ctx[b*NE + col] = ((red[t]+red[t+64])+(red[t+128]+red[t+192])) + bv[col];
}

// ---------------------------------------------------------------------------
// D: out[b] = ctx[b] @ Wo + bo.  grid (16 b, 8 colblocks) x 256, MLP8.
// ---------------------------------------------------------------------------
__global__ void __launch_bounds__(256) kernD(
    const float* __restrict__ Wo, const float* __restrict__ bo,
    float* __restrict__ out)
{
    __shared__ float cs[NE];
    __shared__ float red[256];
    const int b = blockIdx.x, cb = blockIdx.y, t = threadIdx.x;
    for (int i = t; i < NE; i += 256) cs[i] = g_ctx[b*NE + i];
    __syncthreads();
    const int col = cb*64 + (t & 63), kp = t >> 6;
    const float* c  = cs + kp*128;
    const float* wo = Wo + (size_t)(kp*128)*NE + col;
    float s0=0,s1=0,s2=0,s3=0,s4=0,s5=0,s6=0,s7=0;
    #pragma unroll 4
    for (int j = 0; j < 128; j += 8) {
        s0 = fmaf(c[j+0], wo[(size_t)(j+0)*NE], s0);
        s1 = fmaf(c[j+1], wo[(size_t)(j+1)*NE], s1);
        s2 = fmaf(c[j+2], wo[(size_t)(j+2)*NE], s2);
        s3 = fmaf(c[j+3], wo[(size_t)(j+3)*NE], s3);
        s4 = fmaf(c[j+4], wo[(size_t)(j+4)*NE], s4);
        s5 = fmaf(c[j+5], wo[(size_t)(j+5)*NE], s5);
        s6 = fmaf(c[j+6], wo[(size_t)(j+6)*NE], s6);
        s7 = fmaf(c[j+7], wo[(size_t)(j+7)*NE], s7);
    }
    red[t] = ((s0+s1)+(s2+s3))+((s4+s5)+(s6+s7));
    __syncthreads();
    if (t < 64)
        out[b*NE + col] = ((red[t]+red[t+64])+(red[t+128]+red[t+192])) + bo[col];
}

// ---------------------------------------------------------------------------
extern "C" void kernel_launch(void* const* d_in, const int* in_sizes, int n_in,
                              void* d_out, int out_size)
{
    (void)in_sizes; (void)n_in; (void)out_size;
    const float* query = (const float*)d_in[0];
    const float* kv    = (const float*)d_in[1];
    const float* Wq    = (const float*)d_in[2];
    const float* bq    = (const float*)d_in[3];
    const float* Wk    = (const float*)d_in[4];
    // d_in[5] = bk: softmax-invariant, unused
    const float* Wv    = (const float*)d_in[6];
    const float* bv    = (const float*)d_in[7];
    const float* Wo    = (const float*)d_in[8];
    const float* bo    = (const float*)d_in[9];
    float* out = (float*)d_out;

    const size_t shmB = (size_t)(3*TILE*NKV + 128) * sizeof(float);
    cudaFuncSetAttribute(kernB, cudaFuncAttributeMaxDynamicSharedMemorySize, (int)shmB);

    kernA1<<<dim3(NB, 8), 256>>>(query, Wq, bq);
    kernA2<<<dim3(8, NH), 256>>>(Wk);
    kernB <<<dim3(NCHUNK, NB), TB, shmB>>>(kv);
    kernC1<<<64, 256>>>();
    kernC2<<<dim3(NB, NH), 256>>>(Wv, bv);
    kernD <<<dim3(NB, 8), 256>>>(Wo, bo, out);
}

// round 10
// speedup vs baseline: 1.1441x; 1.0219x over previous
#include <cuda_runtime.h>
#include <math.h>

// Problem shape (fixed by the reference)
#define NB     16
#define NS     8192
#define NKV    512
#define NE     512
#define NH     8
#define ND     64
#define NCHUNK 8
#define CHUNK  1024
#define TILE   32
#define NTILES (CHUNK/TILE)   // 32
#define TB     256

// Scratch (device globals; allocations forbidden)
__device__ __align__(16) float g_q[NB*NE];
__device__ __align__(16) float g_P[NB*NH*NKV];
__device__ __align__(16) float g_partC[(size_t)NB*NCHUNK*NH*NKV];
__device__ __align__(16) float g_partZ[NB*NCHUNK*NH];
__device__ __align__(16) float g_cbar[NB*NH*NKV];
__device__ __align__(16) float g_ctx[NB*NE];

// ---- packed f32x2 helpers ----
typedef unsigned long long u64;
__device__ __forceinline__ u64 ffma2(u64 a, u64 b, u64 c) {
    u64 d;
    asm("fma.rn.f32x2 %0, %1, %2, %3;" : "=l"(d) : "l"(a), "l"(b), "l"(c));
    return d;
}
__device__ __forceinline__ float lo2(u64 v){ return __uint_as_float((unsigned)v); }
__device__ __forceinline__ float hi2(u64 v){ return __uint_as_float((unsigned)(v>>32)); }
__device__ __forceinline__ u64 dup2(float v){
    u64 r; asm("mov.b64 %0, {%1, %1};" : "=l"(r) : "f"(v)); return r;
}
__device__ __forceinline__ void cpa16(unsigned dst, const void* src){
    asm volatile("cp.async.cg.shared.global [%0], [%1], 16;" :: "r"(dst), "l"(src));
}

// ---------------------------------------------------------------------------
// A1: q[b,e] = query[b,:] @ Wq[:,e] + bq[e].
// grid (16 b, 8 eblocks of 64) x 256 = 64 cols x 4-way split-K, MLP8.
// ---------------------------------------------------------------------------
__global__ void __launch_bounds__(256) kernA1(
    const float* __restrict__ query, const float* __restrict__ Wq,
    const float* __restrict__ bq)
{
    __shared__ float qs[NKV];
    __shared__ float red[256];
    const int b = blockIdx.x, eb = blockIdx.y, t = threadIdx.x;
    for (int i = t; i < NKV; i += 256) qs[i] = query[b*NKV + i];
    __syncthreads();
    const int e = eb*64 + (t & 63), kp = t >> 6;
    const float* q  = qs + kp*128;
    const float* wq = Wq + (size_t)(kp*128)*NE + e;
    float s0=0,s1=0,s2=0,s3=0,s4=0,s5=0,s6=0,s7=0;
    #pragma unroll 4
    for (int j = 0; j < 128; j += 8) {
        s0 = fmaf(q[j+0], wq[(size_t)(j+0)*NE], s0);
        s1 = fmaf(q[j+1], wq[(size_t)(j+1)*NE], s1);
        s2 = fmaf(q[j+2], wq[(size_t)(j+2)*NE], s2);
        s3 = fmaf(q[j+3], wq[(size_t)(j+3)*NE], s3);
        s4 = fmaf(q[j+4], wq[(size_t)(j+4)*NE], s4);
        s5 = fmaf(q[j+5], wq[(size_t)(j+5)*NE], s5);
        s6 = fmaf(q[j+6], wq[(size_t)(j+6)*NE], s6);
        s7 = fmaf(q[j+7], wq[(size_t)(j+7)*NE], s7);
    }
    red[t] = ((s0+s1)+(s2+s3))+((s4+s5)+(s6+s7));
    __syncthreads();
    if (t < 64)
        g_q[b*NE + e] = ((red[t]+red[t+64])+(red[t+128]+red[t+192])) + bq[e];
}

// ---------------------------------------------------------------------------
// A2: P[b,h,j] = 0.125 * sum_d g_q[b,h*64+d] * Wk[j,h*64+d]
// ---------------------------------------------------------------------------
__global__ void __launch_bounds__(256) kernA2(const float* __restrict__ Wk)
{
    __shared__ float wks[64*65];
    __shared__ float qhs[16*64];
    const int jb = blockIdx.x, h = blockIdx.y, t = threadIdx.x;

    for (int i = t; i < 64*16; i += 256) {
        int j = i >> 4, d4 = i & 15;
        float4 v = *(const float4*)(Wk + (size_t)(jb*64 + j)*NE + h*ND + d4*4);
        wks[j*65 + d4*4+0] = v.x; wks[j*65 + d4*4+1] = v.y;
        wks[j*65 + d4*4+2] = v.z; wks[j*65 + d4*4+3] = v.w;
    }
    for (int i = t; i < 16*64; i += 256) {
        int bb = i >> 6, d = i & 63;
        qhs[bb*64 + d] = g_q[bb*NE + h*ND + d];
    }
    __syncthreads();

    const int j = t & 63, bg = t >> 6;
    float acc[4] = {0.f,0.f,0.f,0.f};
    const float* wr = wks + j*65;
    #pragma unroll
    for (int d = 0; d < 64; ++d) {
        float wv = wr[d];
        #pragma unroll
        for (int bb = 0; bb < 4; ++bb)
            acc[bb] = fmaf(wv, qhs[(bg*4 + bb)*64 + d], acc[bb]);
    }
    #pragma unroll
    for (int bb = 0; bb < 4; ++bb)
        g_P[((size_t)(bg*4 + bb)*NH + h)*NKV + jb*64 + j] = acc[bb]*0.125f;
}

// ---------------------------------------------------------------------------
// B: fused single-phase pass over kv. 256 threads / 8 warps (2 per SMSP).
// warp w: rows rb*8..+7 (rb=w>>1), heads hg*4..+3 (hg=w&1).
// Rows processed in FOUR 2-row groups (keeps live regs ~210 < 256: no
// spills). Per group: kv rows in registers feed both the logit dot
// (fold16/fold8 + 3-stage reduce-scatter over 8) and the weighted
// accumulation into a 4-head x 16-col register tile (w broadcast fused).
// No-max softmax (|logit| < ~3). Triple-buffered cp.async ring.
// ---------------------------------------------------------------------------
__global__ void __launch_bounds__(TB, 1) kernB(const float* __restrict__ kv)
{
    extern __shared__ float sh[];
    float* kvs = sh;                 // [3][TILE][NKV] (reused as reduce buffer)
    float* zs  = sh + 3*TILE*NKV;    // [64]

    const int tid  = threadIdx.x;
    const int wid  = tid >> 5, lane = tid & 31;
    const int rb = wid >> 1, hg = wid & 1;
    const int chunk = blockIdx.x, b = blockIdx.y;

    // P slice in registers: 4 heads x 4 chunks x 4 floats (per lane)
    u64 Pr[4][4][2];
    #pragma unroll
    for (int h = 0; h < 4; ++h)
        #pragma unroll
        for (int c = 0; c < 4; ++c) {
            const float* p = g_P + ((size_t)b*NH + hg*4 + h)*NKV + c*128 + lane*4;
            ulonglong2 v = *(const ulonglong2*)p;
            Pr[h][c][0] = v.x; Pr[h][c][1] = v.y;
        }

    u64 acc[4][4][2];
    #pragma unroll
    for (int h = 0; h < 4; ++h)
        #pragma unroll
        for (int c = 0; c < 4; ++c) { acc[h][c][0] = 0ull; acc[h][c][1] = 0ull; }
    float zacc = 0.f;

    const unsigned kvs_u = (unsigned)__cvta_generic_to_shared(kvs);
    const float4* src_base = (const float4*)kv
        + ((size_t)b*NS + (size_t)chunk*CHUNK)*(NKV/4);

    // prologue: stage tiles 0 and 1
    #pragma unroll
    for (int pt = 0; pt < 2; ++pt) {
        const float4* s = src_base + (size_t)pt*TILE*(NKV/4);
        unsigned dst = kvs_u + (unsigned)(pt*TILE*NKV*4);
        #pragma unroll
        for (int k = 0; k < (TILE*NKV/4)/TB; ++k) {
            int i = tid + k*TB;
            cpa16(dst + (unsigned)i*16u, s + i);
        }
        asm volatile("cp.async.commit_group;");
    }

    for (int t = 0; t < NTILES; ++t) {
        if (t < NTILES-1) asm volatile("cp.async.wait_group 1;");
        else              asm volatile("cp.async.wait_group 0;");
        __syncthreads();

        if (t + 2 < NTILES) {   // stage t+2 into buffer (t+2)%3
            const float4* s = src_base + (size_t)(t+2)*TILE*(NKV/4);
            unsigned dst = kvs_u + (unsigned)(((t+2)%3)*TILE*NKV*4);
            #pragma unroll
            for (int k = 0; k < (TILE*NKV/4)/TB; ++k) {
                int i = tid + k*TB;
                cpa16(dst + (unsigned)i*16u, s + i);
            }
            asm volatile("cp.async.commit_group;");
        }

        const float* kbw = kvs + (t%3)*TILE*NKV + rb*8*NKV;
        #pragma unroll
        for (int g = 0; g < 4; ++g) {
            // load 2 rows into registers (reused by both stages)
            ulonglong2 x[2][4];
            #pragma unroll
            for (int r = 0; r < 2; ++r)
                #pragma unroll
                for (int c = 0; c < 4; ++c)
                    x[r][c] = *(const ulonglong2*)(kbw + (g*2+r)*NKV + c*128 + lane*4);

            // logits: 2 rows x 4 heads
            u64 la[2][4];
            #pragma unroll
            for (int r = 0; r < 2; ++r)
                #pragma unroll
                for (int h = 0; h < 4; ++h) la[r][h] = 0ull;
            #pragma unroll
            for (int c = 0; c < 4; ++c)
                #pragma unroll
                for (int r = 0; r < 2; ++r)
                    #pragma unroll
                    for (int h = 0; h < 4; ++h) {
                        la[r][h] = ffma2(x[r][c].x, Pr[h][c][0], la[r][h]);
                        la[r][h] = ffma2(x[r][c].y, Pr[h][c][1], la[r][h]);
                    }
            float v[8];
            #pragma unroll
            for (int r = 0; r < 2; ++r)
                #pragma unroll
                for (int h = 0; h < 4; ++h)
                    v[r*4+h] = lo2(la[r][h]) + hi2(la[r][h]);
            // fold lane bits 4 and 3, then reduce-scatter over 8 lanes:
            // lane l (l<8) ends with full logit of index l = r*4+h
            #pragma unroll
            for (int j = 0; j < 8; ++j) v[j] += __shfl_xor_sync(0xffffffffu, v[j], 16);
            #pragma unroll
            for (int j = 0; j < 8; ++j) v[j] += __shfl_xor_sync(0xffffffffu, v[j], 8);
            #pragma unroll
            for (int half = 4; half >= 1; half >>= 1) {
                const bool up = (lane & half) != 0;
                #pragma unroll
                for (int j = 0; j < half; ++j) {
                    float mine   = up ? v[j+half] : v[j];
                    float theirs = up ? v[j]      : v[j+half];
                    v[j] = mine + __shfl_xor_sync(0xffffffffu, theirs, half);
                }
            }
            float w = __expf(v[0]);        // idx = lane&7: r=(idx>>2), h=idx&3
            if (lane < 8) zacc += w;
            // weighted accumulation; w broadcast fused per (r,h)
            #pragma unroll
            for (int r = 0; r < 2; ++r)
                #pragma unroll
                for (int h = 0; h < 4; ++h) {
                    u64 wd = dup2(__shfl_sync(0xffffffffu, w, r*4 + h));
                    #pragma unroll
                    for (int c = 0; c < 4; ++c) {
                        acc[h][c][0] = ffma2(wd, x[r][c].x, acc[h][c][0]);
                        acc[h][c][1] = ffma2(wd, x[r][c].y, acc[h][c][1]);
                    }
                }
        }
    }

    // ---- epilogue: cross-warp reduce via smem (kvs is free now) ----
    // Each warp owns 2048 floats: [4 heads][512 cols]; 8 warps = 16384
    // floats < 49152-float kv ring: in-bounds.
    __syncthreads();
    {
        float* red = kvs + wid*2048;
        #pragma unroll
        for (int h = 0; h < 4; ++h)
            #pragma unroll
            for (int c = 0; c < 4; ++c)
                *(ulonglong2*)(red + h*NKV + c*128 + lane*4)
                    = make_ulonglong2(acc[h][c][0], acc[h][c][1]);
        if (lane < 8) zs[wid*8 + lane] = zacc;
    }
    __syncthreads();

    const int part = b*NCHUNK + chunk;
    {
        float4* pc = (float4*)(g_partC + (size_t)part*NH*NKV);
        const float4* redv = (const float4*)kvs;   // warp stride 512 float4
        for (int s = tid; s < NH*NKV/4; s += TB) {
            const int h = s >> 7, col4 = s & 127;
            const int hg2 = h >> 2, hl = h & 3;    // warp = rbi*2 + hg2
            float4 a0 = redv[(0*2+hg2)*512 + hl*128 + col4];
            float4 a1 = redv[(1*2+hg2)*512 + hl*128 + col4];
            float4 a2 = redv[(2*2+hg2)*512 + hl*128 + col4];
            float4 a3 = redv[(3*2+hg2)*512 + hl*128 + col4];
            a0.x += a1.x + a2.x + a3.x;
            a0.y += a1.y + a2.y + a3.y;
            a0.z += a1.z + a2.z + a3.z;
            a0.w += a1.w + a2.w + a3.w;
            pc[s] = a0;
        }
    }
    if (tid < NH) {
        const int hg2 = tid >> 2, hl = tid & 3;
        float Z = 0.f;
        #pragma unroll
        for (int rbi = 0; rbi < 4; ++rbi) {
            const int wi = rbi*2 + hg2;
            Z += zs[wi*8 + hl] + zs[wi*8 + 4 + hl];
        }
        g_partZ[part*NH + tid] = Z;
    }
}

// ---------------------------------------------------------------------------
// C1: cbar[b,h,j] = (sum_i partC[b,i,h,j]) / Z[b,h].  grid 64 x 256
// ---------------------------------------------------------------------------
__global__ void __launch_bounds__(256) kernC1()
{
    const int idx = blockIdx.x*256 + threadIdx.x;      // 16384 float4 slots
    const int b = idx >> 10, rem = idx & 1023, h = rem >> 7, j4 = rem & 127;
    float Z = 0.f;
    #pragma unroll
    for (int i = 0; i < NCHUNK; ++i) Z += g_partZ[(b*NCHUNK + i)*NH + h];
    const float invZ = 1.0f / Z;
    float4 s = make_float4(0.f,0.f,0.f,0.f);
    #pragma unroll
    for (int i = 0; i < NCHUNK; ++i) {
        const float4* p = (const float4*)(g_partC + (((size_t)(b*NCHUNK + i)*NH + h) << 9));
        float4 v = p[j4];
        s.x += v.x; s.y += v.y; s.z += v.z; s.w += v.w;
    }
    s.x *= invZ; s.y *= invZ; s.z *= invZ; s.w *= invZ;
    ((float4*)g_cbar)[((size_t)(b*NH + h) << 7) + j4] = s;
}

// ---------------------------------------------------------------------------
// C2: ctx[b, h*64+col] = cbar[b,h,:] @ Wv[:, h*64+col] + bv.
// grid (16 b, 8 h) x 256 = 64 cols x 4-way split-K, MLP8.
// ---------------------------------------------------------------------------
__global__ void __launch_bounds__(256) kernC2(
    const float* __restrict__ Wv, const float* __restrict__ bv)
{
    __shared__ float cb_s[NKV];
    __shared__ float red[256];
    const int b = blockIdx.x, h = blockIdx.y, t = threadIdx.x;
    for (int i = t; i < NKV; i += 256) cb_s[i] = g_cbar[(size_t)(b*NH + h)*NKV + i];
    __syncthreads();
    const int col = h*64 + (t & 63), kp = t >> 6;
    const float* c  = cb_s + kp*128;
    const float* wv = Wv + (size_t)(kp*128)*NE + col;
    float s0=0,s1=0,s2=0,s3=0,s4=0,s5=0,s6=0,s7=0;
    #pragma unroll 4
    for (int j = 0; j < 128; j += 8) {
        s0 = fmaf(c[j+0], wv[(size_t)(j+0)*NE], s0);
        s1 = fmaf(c[j+1], wv[(size_t)(j+1)*NE], s1);
        s2 = fmaf(c[j+2], wv[(size_t)(j+2)*NE], s2);
        s3 = fmaf(c[j+3], wv[(size_t)(j+3)*NE], s3);
        s4 = fmaf(c[j+4], wv[(size_t)(j+4)*NE], s4);
        s5 = fmaf(c[j+5], wv[(size_t)(j+5)*NE], s5);
        s6 = fmaf(c[j+6], wv[(size_t)(j+6)*NE], s6);
        s7 = fmaf(c[j+7], wv[(size_t)(j+7)*NE], s7);
    }
    red[t] = ((s0+s1)+(s2+s3))+((s4+s5)+(s6+s7));
    __syncthreads();
    if (t < 64)
        g_ctx[b*NE + col] = ((red[t]+red[t+64])+(red[t+128]+red[t+192])) + bv[col];
}

// ---------------------------------------------------------------------------
// D: out[b] = ctx[b] @ Wo + bo.  grid (16 b, 8 colblocks) x 256, MLP8.
// ---------------------------------------------------------------------------
__global__ void __launch_bounds__(256) kernD(
    const float* __restrict__ Wo, const float* __restrict__ bo,
    float* __restrict__ out)
{
    __shared__ float cs[NE];
    __shared__ float red[256];
    const int b = blockIdx.x, cb = blockIdx.y, t = threadIdx.x;
    for (int i = t; i < NE; i += 256) cs[i] = g_ctx[b*NE + i];
    __syncthreads();
    const int col = cb*64 + (t & 63), kp = t >> 6;
    const float* c  = cs + kp*128;
    const float* wo = Wo + (size_t)(kp*128)*NE + col;
    float s0=0,s1=0,s2=0,s3=0,s4=0,s5=0,s6=0,s7=0;
    #pragma unroll 4
    for (int j = 0; j < 128; j += 8) {
        s0 = fmaf(c[j+0], wo[(size_t)(j+0)*NE], s0);
        s1 = fmaf(c[j+1], wo[(size_t)(j+1)*NE], s1);
        s2 = fmaf(c[j+2], wo[(size_t)(j+2)*NE], s2);
        s3 = fmaf(c[j+3], wo[(size_t)(j+3)*NE], s3);
        s4 = fmaf(c[j+4], wo[(size_t)(j+4)*NE], s4);
        s5 = fmaf(c[j+5], wo[(size_t)(j+5)*NE], s5);
        s6 = fmaf(c[j+6], wo[(size_t)(j+6)*NE], s6);
        s7 = fmaf(c[j+7], wo[(size_t)(j+7)*NE], s7);
    }
    red[t] = ((s0+s1)+(s2+s3))+((s4+s5)+(s6+s7));
    __syncthreads();
    if (t < 64)
        out[b*NE + col] = ((red[t]+red[t+64])+(red[t+128]+red[t+192])) + bo[col];
}

// ---------------------------------------------------------------------------
extern "C" void kernel_launch(void* const* d_in, const int* in_sizes, int n_in,
                              void* d_out, int out_size)
{
    (void)in_sizes; (void)n_in; (void)out_size;
    const float* query = (const float*)d_in[0];
    const float* kv    = (const float*)d_in[1];
    const float* Wq    = (const float*)d_in[2];
    const float* bq    = (const float*)d_in[3];
    const float* Wk    = (const float*)d_in[4];
    // d_in[5] = bk: softmax-invariant, unused
    const float* Wv    = (const float*)d_in[6];
    const float* bv    = (const float*)d_in[7];
    const float* Wo    = (const float*)d_in[8];
    const float* bo    = (const float*)d_in[9];
    float* out = (float*)d_out;

    const size_t shmB = (size_t)(3*TILE*NKV + 64) * sizeof(float);
    cudaFuncSetAttribute(kernB, cudaFuncAttributeMaxDynamicSharedMemorySize, (int)shmB);

    kernA1<<<dim3(NB, 8), 256>>>(query, Wq, bq);
    kernA2<<<dim3(8, NH), 256>>>(Wk);
    kernB <<<dim3(NCHUNK, NB), TB, shmB>>>(kv);
    kernC1<<<64, 256>>>();
    kernC2<<<dim3(NB, NH), 256>>>(Wv, bv);
    kernD <<<dim3(NB, 8), 256>>>(Wo, bo, out);
}